// round 11
// baseline (speedup 1.0000x reference)
#include <cuda_runtime.h>

// LIF neuron scan, round 10: half tiles -> 2 persistent CTAs/SM.
//
// Round-9 analysis: per-iter wall ~4030 cyc vs ~3300 cyc of pure DRAM time;
// ~700 cyc of per-CTA serialization (cp_wait stall, syncs, issue burst,
// compute tail) exposed because only 1 CTA/SM was resident. Fix: shrink the
// tile to 64 rows (25 KB), 3-buffer ring = 75 KB/CTA -> 2 CTAs/SM (grid 296).
// The co-resident CTA's DMA traffic fills the other's bubbles; the proven
// async load (cp.async) / async bulk-store ring is otherwise unchanged.

#define T_STEPS   100
#define T_VEC     (T_STEPS / 4)        // 25 float4 per row
#define ROWS_CTA  64
#define TILE_V4   (ROWS_CTA * T_VEC)   // 1600 float4 = 25 KB
#define TILE_BYTES (TILE_V4 * 16)
#define GRID_P    296                  // 2 persistent CTAs per SM

__device__ __forceinline__ void cp_async16(float4* smem_dst, const float4* gmem_src) {
    unsigned saddr = (unsigned)__cvta_generic_to_shared(smem_dst);
    asm volatile("cp.async.cg.shared.global [%0], [%1], 16;\n" :: "r"(saddr), "l"(gmem_src));
}
__device__ __forceinline__ void cp_commit() {
    asm volatile("cp.async.commit_group;\n");
}
template <int N>
__device__ __forceinline__ void cp_wait() {
    asm volatile("cp.async.wait_group %0;\n" :: "n"(N));
}

// Bulk smem -> gmem DMA (separate group mechanism from cp.async above).
__device__ __forceinline__ void bulk_store(float4* gmem_dst, const float4* smem_src, unsigned bytes) {
    unsigned saddr = (unsigned)__cvta_generic_to_shared(smem_src);
    asm volatile("cp.async.bulk.global.shared::cta.bulk_group [%0], [%1], %2;\n"
                 :: "l"(gmem_dst), "r"(saddr), "r"(bytes) : "memory");
}
__device__ __forceinline__ void bulk_commit() {
    asm volatile("cp.async.bulk.commit_group;\n");
}
template <int N>
__device__ __forceinline__ void bulk_wait() {
    asm volatile("cp.async.bulk.wait_group %0;\n" :: "n"(N) : "memory");
}
__device__ __forceinline__ void fence_async_proxy() {
    asm volatile("fence.proxy.async.shared::cta;\n" ::: "memory");
}

__global__ __launch_bounds__(ROWS_CTA, 2) void lif_kernel(const float4* __restrict__ x,
                                                          float4* __restrict__ out,
                                                          int ntiles) {
    extern __shared__ float4 smem[];              // [3 * TILE_V4]
    float4* bA = smem;                            // ring: cur, next, spare
    float4* bB = smem + TILE_V4;
    float4* bC = smem + 2 * TILE_V4;

    const int tid    = threadIdx.x;
    const int stride = gridDim.x;

    int tile0 = blockIdx.x;
    if (tile0 >= ntiles) return;

    // Prologue: prefetch first tile into bA.
    {
        const float4* src = x + (long long)tile0 * TILE_V4;
        #pragma unroll
        for (int i = 0; i < T_VEC; ++i)
            cp_async16(&bA[tid + ROWS_CTA * i], &src[tid + ROWS_CTA * i]);
        cp_commit();
    }

    for (int tile = tile0; tile < ntiles; tile += stride) {
        float4* cur = bA;
        float4* nxt = bB;

        int next = tile + stride;
        if (next < ntiles) {
            // nxt's bulk store was issued 2 iterations ago. Outstanding stores
            // now: {iter-2 (on nxt), iter-1}. wait<1> drains iter-2, leaves
            // iter-1 in flight -> safe to overwrite nxt, store stays async.
            if (tid == 0) bulk_wait<1>();
            __syncthreads();

            const float4* src = x + (long long)next * TILE_V4;
            #pragma unroll
            for (int i = 0; i < T_VEC; ++i)
                cp_async16(&nxt[tid + ROWS_CTA * i], &src[tid + ROWS_CTA * i]);
            cp_commit();
            cp_wait<1>();       // current tile's load group has landed
        } else {
            cp_wait<0>();
        }
        __syncthreads();

        // ---- Compute: serial LIF scan of this thread's row, in place ----
        const float decay = 0.5f;
        const float vth   = 0.5f;
        float v = 0.0f;
        float4* __restrict__ row = cur + tid * T_VEC;

        #pragma unroll
        for (int i = 0; i < T_VEC; ++i) {
            float4 xi = row[i];
            float4 so;

            v = fmaf(v, decay, xi.x);
            so.x = (v > vth) ? 1.0f : 0.0f;
            v = fmaf(so.x, -vth, v);

            v = fmaf(v, decay, xi.y);
            so.y = (v > vth) ? 1.0f : 0.0f;
            v = fmaf(so.y, -vth, v);

            v = fmaf(v, decay, xi.z);
            so.z = (v > vth) ? 1.0f : 0.0f;
            v = fmaf(so.z, -vth, v);

            v = fmaf(v, decay, xi.w);
            so.w = (v > vth) ? 1.0f : 0.0f;
            v = fmaf(so.w, -vth, v);

            row[i] = so;
        }

        // Order generic smem writes before the async-proxy bulk read, then
        // fire-and-forget the 25 KB tile store.
        fence_async_proxy();
        __syncthreads();
        if (tid == 0) {
            bulk_store(out + (long long)tile * TILE_V4, cur, TILE_BYTES);
            bulk_commit();
        }

        // Rotate ring: A<-B (next tile's data), B<-C (free), C<-A (storing).
        float4* t = bA; bA = bB; bB = bC; bC = t;
    }

    // Drain outstanding bulk stores before exit.
    if (tid == 0) bulk_wait<0>();
}

extern "C" void kernel_launch(void* const* d_in, const int* in_sizes, int n_in,
                              void* d_out, int out_size) {
    const float4* x = (const float4*)d_in[0];
    float4* out = (float4*)d_out;

    int n_rows = in_sizes[0] / T_STEPS;          // 524288
    int ntiles = n_rows / ROWS_CTA;              // 8192

    size_t smem_bytes = 3 * TILE_V4 * sizeof(float4);   // 75 KB
    static bool attr_set = false;
    if (!attr_set) {
        cudaFuncSetAttribute(lif_kernel, cudaFuncAttributeMaxDynamicSharedMemorySize,
                             (int)smem_bytes);
        attr_set = true;
    }
    int grid = ntiles < GRID_P ? ntiles : GRID_P;
    lif_kernel<<<grid, ROWS_CTA, smem_bytes>>>(x, out, ntiles);
}

// round 12
// speedup vs baseline: 1.0013x; 1.0013x over previous
#include <cuda_runtime.h>

// LIF neuron scan, round 11: 4-buffer ring, prefetch distance 2.
//
// r9 residual: per-iter wall ~4100 cyc vs ~2400 cyc DMA -> 30% exposed on the
// serial chain "wait load(k) -> compute(k) -> store(k)", because load(k) was
// issued only 1 iteration ahead into a saturated DRAM system. Fix: 4 x 50 KB
// ring (200 KB, 1 CTA/SM), issue load(k+2) each iter, cp_wait<2> guards
// load(k) which now has 2 full iterations of slack -> steady-state no-op.
// Invariant: exactly ONE cp.async commit per iteration (empty groups in the
// tail) so wait<2> always corresponds to "load(k) landed".
// Store safety: prefetch target buf[(j+2)%4] held tile j-2; outstanding
// stores {j-2, j-1}; bulk_wait<1> drains j-2, keeps j-1 async.

#define T_STEPS   100
#define T_VEC     (T_STEPS / 4)        // 25 float4 per row
#define ROWS_CTA  128
#define TILE_V4   (ROWS_CTA * T_VEC)   // 3200 float4 = 50 KB
#define TILE_BYTES (TILE_V4 * 16)
#define RING      4                    // 4 x 50 KB = 200 KB
#define GRID_P    148                  // 1 persistent CTA per SM

__device__ __forceinline__ void cp_async16(float4* smem_dst, const float4* gmem_src) {
    unsigned saddr = (unsigned)__cvta_generic_to_shared(smem_dst);
    asm volatile("cp.async.cg.shared.global [%0], [%1], 16;\n" :: "r"(saddr), "l"(gmem_src));
}
__device__ __forceinline__ void cp_commit() {
    asm volatile("cp.async.commit_group;\n");
}
template <int N>
__device__ __forceinline__ void cp_wait() {
    asm volatile("cp.async.wait_group %0;\n" :: "n"(N));
}

__device__ __forceinline__ void bulk_store(float4* gmem_dst, const float4* smem_src, unsigned bytes) {
    unsigned saddr = (unsigned)__cvta_generic_to_shared(smem_src);
    asm volatile("cp.async.bulk.global.shared::cta.bulk_group [%0], [%1], %2;\n"
                 :: "l"(gmem_dst), "r"(saddr), "r"(bytes) : "memory");
}
__device__ __forceinline__ void bulk_commit() {
    asm volatile("cp.async.bulk.commit_group;\n");
}
template <int N>
__device__ __forceinline__ void bulk_wait() {
    asm volatile("cp.async.bulk.wait_group %0;\n" :: "n"(N) : "memory");
}
__device__ __forceinline__ void fence_async_proxy() {
    asm volatile("fence.proxy.async.shared::cta;\n" ::: "memory");
}

__global__ __launch_bounds__(ROWS_CTA, 1) void lif_kernel(const float4* __restrict__ x,
                                                          float4* __restrict__ out,
                                                          int ntiles) {
    extern __shared__ float4 smem[];              // [RING * TILE_V4]

    const int tid    = threadIdx.x;
    const int stride = gridDim.x;

    const int tile0 = blockIdx.x;
    if (tile0 >= ntiles) return;

    // Prologue: prefetch tiles tile0 and tile0+stride (2 committed groups).
    #pragma unroll
    for (int d = 0; d < 2; ++d) {
        long long t = tile0 + (long long)d * stride;
        if (t < ntiles) {
            const float4* src = x + t * TILE_V4;
            float4* dst = smem + d * TILE_V4;
            #pragma unroll
            for (int i = 0; i < T_VEC; ++i)
                cp_async16(&dst[tid + ROWS_CTA * i], &src[tid + ROWS_CTA * i]);
        }
        cp_commit();
    }

    int j = 0;
    for (long long tile = tile0; tile < ntiles; tile += stride, ++j) {
        float4* cur = smem + (j & 3) * TILE_V4;
        float4* pre = smem + ((j + 2) & 3) * TILE_V4;

        // Free the prefetch target: its tile (j-2) store is the oldest of the
        // (at most) 2 outstanding bulk stores.
        if (tid == 0) bulk_wait<1>();
        __syncthreads();

        // Issue load(k+2); ALWAYS commit (empty group in the tail) to keep
        // the group-count invariant for cp_wait<2>.
        long long t2 = tile + 2LL * stride;
        if (t2 < ntiles) {
            const float4* src = x + t2 * TILE_V4;
            #pragma unroll
            for (int i = 0; i < T_VEC; ++i)
                cp_async16(&pre[tid + ROWS_CTA * i], &src[tid + ROWS_CTA * i]);
        }
        cp_commit();

        // <=2 groups outstanding leaves only (k+1),(k+2): load(k) has landed.
        cp_wait<2>();
        __syncthreads();

        // ---- Compute: serial LIF scan of this thread's row, in place ----
        const float decay = 0.5f;
        const float vth   = 0.5f;
        float v = 0.0f;
        float4* __restrict__ row = cur + tid * T_VEC;

        #pragma unroll
        for (int i = 0; i < T_VEC; ++i) {
            float4 xi = row[i];
            float4 so;

            v = fmaf(v, decay, xi.x);
            so.x = (v > vth) ? 1.0f : 0.0f;
            v = fmaf(so.x, -vth, v);

            v = fmaf(v, decay, xi.y);
            so.y = (v > vth) ? 1.0f : 0.0f;
            v = fmaf(so.y, -vth, v);

            v = fmaf(v, decay, xi.z);
            so.z = (v > vth) ? 1.0f : 0.0f;
            v = fmaf(so.z, -vth, v);

            v = fmaf(v, decay, xi.w);
            so.w = (v > vth) ? 1.0f : 0.0f;
            v = fmaf(so.w, -vth, v);

            row[i] = so;
        }

        // Order generic smem writes before the async-proxy read, then
        // fire-and-forget the 50 KB tile store.
        fence_async_proxy();
        __syncthreads();
        if (tid == 0) {
            bulk_store(out + tile * TILE_V4, cur, TILE_BYTES);
            bulk_commit();
        }
    }

    // Drain outstanding bulk stores before exit.
    if (tid == 0) bulk_wait<0>();
}

extern "C" void kernel_launch(void* const* d_in, const int* in_sizes, int n_in,
                              void* d_out, int out_size) {
    const float4* x = (const float4*)d_in[0];
    float4* out = (float4*)d_out;

    int n_rows = in_sizes[0] / T_STEPS;          // 524288
    int ntiles = n_rows / ROWS_CTA;              // 4096

    size_t smem_bytes = (size_t)RING * TILE_V4 * sizeof(float4);   // 200 KB
    static bool attr_set = false;
    if (!attr_set) {
        cudaFuncSetAttribute(lif_kernel, cudaFuncAttributeMaxDynamicSharedMemorySize,
                             (int)smem_bytes);
        attr_set = true;
    }
    int grid = ntiles < GRID_P ? ntiles : GRID_P;
    lif_kernel<<<grid, ROWS_CTA, smem_bytes>>>(x, out, ntiles);
}